// round 15
// baseline (speedup 1.0000x reference)
#include <cuda_runtime.h>
#include <math_constants.h>

#define BB 512
#define TT 512
#define KK 64

// 16.7 MB history scratch (argmax index per (b, t, j)), plus per-batch best-last tag.
__device__ unsigned char g_hist[(size_t)BB * TT * KK];
__device__ int g_best[BB];

// ---------------------------------------------------------------------------
// cp.async helpers (LDGSTS on sm_103): 16B global->shared, grouped.
// ---------------------------------------------------------------------------
__device__ __forceinline__ void cp_async16(void* smem_dst, const void* gsrc) {
    unsigned saddr = (unsigned)__cvta_generic_to_shared(smem_dst);
    asm volatile("cp.async.ca.shared.global [%0], [%1], 16;"
                 :: "r"(saddr), "l"(gsrc));
}
__device__ __forceinline__ void cp_commit() {
    asm volatile("cp.async.commit_group;");
}
__device__ __forceinline__ void cp_wait1() {
    asm volatile("cp.async.wait_group 1;");
}

// ---------------------------------------------------------------------------
// Warp-wide exact f32 max via ONE integer redux (sm_80+: redux.sync.max.u32).
// Order-preserving monotonic float->u32 key; exact inverse on the result.
// ---------------------------------------------------------------------------
__device__ __forceinline__ float warp_max_f32_redux(float v) {
    const int i = __float_as_int(v);
    const unsigned key = (i >= 0) ? ((unsigned)i | 0x80000000u)
                                  : (unsigned)(~i);
    unsigned r;
    asm("redux.sync.max.u32 %0, %1, 0xffffffff;" : "=r"(r) : "r"(key));
    const int j = (r & 0x80000000u) ? (int)(r & 0x7FFFFFFFu) : ~(int)r;
    return __int_as_float(j);
}

// ---------------------------------------------------------------------------
// Forward Viterbi: one WARP handles TWO batches (A, B), manually interleaved
// statement-by-statement so each batch's dependency-chain stalls are filled
// by the other batch's independent work (warps issue in order — interleaving
// must be in program order). 2 warps/block share the trans tile; grid 128.
// Per batch (identical semantics to the passing R14 kernel):
//   - emissions via double-buffered cp.async tiles (8 steps/tile), issued 8
//     steps ahead; one commit group carries both batches' tiles.
//   - warp max via single redux.sync.max.u32.
//   - live prev-tag set: compacted ASCENDING index list in shared (int4
//     groups, sentinel idx=64 with score -inf / trans 0), from two ballots.
//     Fused phase-A loop over max(ngA, ngB) groups with min-clamp (duplicate
//     groups cannot update a strict-'>' chain -> exact).
//   - exact pruning: i prunable iff s_i < smax + (Tmin - Tmax) - 0.05; the
//     margin >> accumulated rounding, so a pruned i can never be the argmax,
//     even via first-index ties.
//   - argmax: single strict-'>' chain per j over the ascending list -> exact
//     jnp.argmax first-occurrence semantics.
// ---------------------------------------------------------------------------
__global__ __launch_bounds__(64) void viterbi_forward(
    const float* __restrict__ emissions,   // [B, T, K]
    const int*   __restrict__ mask,        // [B, T]
    const float* __restrict__ start_t,     // [K]
    const float* __restrict__ end_t,       // [K]
    const float* __restrict__ trans)       // [K, K]
{
    const int tid  = threadIdx.x;
    const int lane = tid & 31;
    const int w    = tid >> 5;             // 0..1
    const int bA   = blockIdx.x * 4 + w * 2;
    const int bB   = bA + 1;

    __shared__ __align__(16) float2 tp_sh[KK + 1][32];         // 16.6 KB
    __shared__ __align__(16) float  score_sh[2][2][2][72];     // [w][bat][par]
    __shared__ __align__(16) int    live_sh[2][2][2][72];
    __shared__ __align__(16) float  em_sh[2][2][2][8 * KK];    // [w][bat][buf]
    __shared__ unsigned char smask_sh[2][2][TT];
    __shared__ float red_sh[4];

    const float* emA = emissions + (size_t)bA * TT * KK;
    const float* emB = emissions + (size_t)bB * TT * KK;
    const int*   mkA = mask + (size_t)bA * TT;
    const int*   mkB = mask + (size_t)bB * TT;

    // ---- issue first two tile-pairs (group = {A tile, B tile}) ----
    {
#pragma unroll
        for (int k = 0; k < 4; ++k) {
            cp_async16(&em_sh[w][0][0][k * 128 + lane * 4], emA + k * 128 + lane * 4);
            cp_async16(&em_sh[w][1][0][k * 128 + lane * 4], emB + k * 128 + lane * 4);
        }
        cp_commit();
#pragma unroll
        for (int k = 0; k < 4; ++k) {
            cp_async16(&em_sh[w][0][1][k * 128 + lane * 4], emA + 8 * KK + k * 128 + lane * 4);
            cp_async16(&em_sh[w][1][1][k * 128 + lane * 4], emB + 8 * KK + k * 128 + lane * 4);
        }
        cp_commit();
    }

    // ---- one-time: stage trans (pair layout) + masks, global Tmin/Tmax ----
    float tmn = CUDART_INF_F, tmx = -CUDART_INF_F;
    for (int i = w; i < KK; i += 2) {
        const float a = trans[i * KK + lane];
        const float c = trans[i * KK + 32 + lane];
        tp_sh[i][lane] = make_float2(a, c);
        tmn = fminf(tmn, fminf(a, c));
        tmx = fmaxf(tmx, fmaxf(a, c));
    }
    if (w == 0) tp_sh[KK][lane] = make_float2(0.0f, 0.0f);     // sentinel row
    if (lane == 0) {
        score_sh[w][0][0][KK] = -CUDART_INF_F;
        score_sh[w][0][1][KK] = -CUDART_INF_F;
        score_sh[w][1][0][KK] = -CUDART_INF_F;
        score_sh[w][1][1][KK] = -CUDART_INF_F;
    }
    for (int k = lane; k < TT; k += 32) {
        smask_sh[w][0][k] = (unsigned char)mkA[k];
        smask_sh[w][1][k] = (unsigned char)mkB[k];
    }
#pragma unroll
    for (int d = 16; d; d >>= 1) {
        tmn = fminf(tmn, __shfl_xor_sync(0xFFFFFFFFu, tmn, d));
        tmx = fmaxf(tmx, __shfl_xor_sync(0xFFFFFFFFu, tmx, d));
    }
    if (lane == 0) { red_sh[w] = tmn; red_sh[2 + w] = tmx; }
    __syncthreads();                                            // last block sync
    const float thrD =
        (fminf(red_sh[0], red_sh[1]) - fmaxf(red_sh[2], red_sh[3])) - 0.05f;

    const unsigned lanemask = (1u << lane) - 1u;

    // ---- tile-pair 0 ready ----
    cp_wait1();
    __syncwarp();
    int ebuf = 0;

    // ---- init scores (t = 0) + initial live lists ----
    float s0A = start_t[lane]      + em_sh[w][0][0][lane];
    float s1A = start_t[lane + 32] + em_sh[w][0][0][32 + lane];
    float s0B = start_t[lane]      + em_sh[w][1][0][lane];
    float s1B = start_t[lane + 32] + em_sh[w][1][0][32 + lane];
    int nlA, nlB;
    {
        const float thrA = warp_max_f32_redux(fmaxf(s0A, s1A)) + thrD;
        const float thrB = warp_max_f32_redux(fmaxf(s0B, s1B)) + thrD;
        const unsigned a0 = __ballot_sync(0xFFFFFFFFu, s0A >= thrA);
        const unsigned a1 = __ballot_sync(0xFFFFFFFFu, s1A >= thrA);
        const unsigned b0 = __ballot_sync(0xFFFFFFFFu, s0B >= thrB);
        const unsigned b1 = __ballot_sync(0xFFFFFFFFu, s1B >= thrB);
        nlA = __popc(a0) + __popc(a1);
        nlB = __popc(b0) + __popc(b1);
        score_sh[w][0][0][lane]      = s0A;
        score_sh[w][0][0][lane + 32] = s1A;
        score_sh[w][1][0][lane]      = s0B;
        score_sh[w][1][0][lane + 32] = s1B;
        if ((a0 >> lane) & 1u) live_sh[w][0][0][__popc(a0 & lanemask)] = lane;
        if ((a1 >> lane) & 1u) live_sh[w][0][0][__popc(a0) + __popc(a1 & lanemask)] = lane + 32;
        if ((b0 >> lane) & 1u) live_sh[w][1][0][__popc(b0 & lanemask)] = lane;
        if ((b1 >> lane) & 1u) live_sh[w][1][0][__popc(b0) + __popc(b1 & lanemask)] = lane + 32;
        if (lane < 4) {
            live_sh[w][0][0][nlA + lane] = KK;
            live_sh[w][1][0][nlB + lane] = KK;
        }
        __syncwarp();
    }

    // ---- e / mask for t = 1 ----
    float e0cA = em_sh[w][0][0][KK + lane];
    float e1cA = em_sh[w][0][0][KK + 32 + lane];
    float e0cB = em_sh[w][1][0][KK + lane];
    float e1cB = em_sh[w][1][0][KK + 32 + lane];
    int   mcA  = smask_sh[w][0][1];
    int   mcB  = smask_sh[w][1][1];

    unsigned char* hpA = g_hist + ((size_t)bA * TT + 1) * KK;
    unsigned char* hpB = g_hist + ((size_t)bB * TT + 1) * KK;

    int p = 0;
    for (int t = 1; t < TT; ++t) {
        // ---- tile boundary: t+1 enters a new 8-step tile (both batches) ----
        if ((t & 7) == 7) {
            const int nbase = (t + 9 <= TT - 8) ? (t + 9) : (TT - 8);
            float* dA = &em_sh[w][0][ebuf][0];
            float* dB = &em_sh[w][1][ebuf][0];
            const float* sA = emA + (size_t)nbase * KK;
            const float* sB = emB + (size_t)nbase * KK;
#pragma unroll
            for (int k = 0; k < 4; ++k) {
                cp_async16(dA + k * 128 + lane * 4, sA + k * 128 + lane * 4);
                cp_async16(dB + k * 128 + lane * 4, sB + k * 128 + lane * 4);
            }
            cp_commit();
            cp_wait1();
            __syncwarp();
            ebuf ^= 1;
        }

        // ---- phase A, fused & interleaved over both batches ----
        const float* scA = score_sh[w][0][p];
        const float* scB = score_sh[w][1][p];
        const int4*  lvA = (const int4*)live_sh[w][0][p];
        const int4*  lvB = (const int4*)live_sh[w][1][p];
        const int ngA = (nlA + 3) >> 2;
        const int ngB = (nlB + 3) >> 2;
        const int ng  = ngA > ngB ? ngA : ngB;

        float bst0A = -CUDART_INF_F, bst1A = -CUDART_INF_F;
        float bst0B = -CUDART_INF_F, bst1B = -CUDART_INF_F;
        int   bid0A = 0, bid1A = 0, bid0B = 0, bid1B = 0;

        for (int g = 0; g < ng; ++g) {
            const int4 ivA = lvA[g < ngA ? g : ngA - 1];   // dup groups inert
            const int4 ivB = lvB[g < ngB ? g : ngB - 1];
            // loads first (A then B) so both batches' LDS latencies overlap
            const float  sAx = scA[ivA.x], sAy = scA[ivA.y];
            const float  sAz = scA[ivA.z], sAw = scA[ivA.w];
            const float  sBx = scB[ivB.x], sBy = scB[ivB.y];
            const float  sBz = scB[ivB.z], sBw = scB[ivB.w];
            const float2 tAx = tp_sh[ivA.x][lane], tAy = tp_sh[ivA.y][lane];
            const float2 tAz = tp_sh[ivA.z][lane], tAw = tp_sh[ivA.w][lane];
            const float2 tBx = tp_sh[ivB.x][lane], tBy = tp_sh[ivB.y][lane];
            const float2 tBz = tp_sh[ivB.z][lane], tBw = tp_sh[ivB.w][lane];

            const float vA0x = (sAx + tAx.x) + e0cA, vA1x = (sAx + tAx.y) + e1cA;
            const float vB0x = (sBx + tBx.x) + e0cB, vB1x = (sBx + tBx.y) + e1cB;
            const float vA0y = (sAy + tAy.x) + e0cA, vA1y = (sAy + tAy.y) + e1cA;
            const float vB0y = (sBy + tBy.x) + e0cB, vB1y = (sBy + tBy.y) + e1cB;
            const float vA0z = (sAz + tAz.x) + e0cA, vA1z = (sAz + tAz.y) + e1cA;
            const float vB0z = (sBz + tBz.x) + e0cB, vB1z = (sBz + tBz.y) + e1cB;
            const float vA0w = (sAw + tAw.x) + e0cA, vA1w = (sAw + tAw.y) + e1cA;
            const float vB0w = (sBw + tBw.x) + e0cB, vB1w = (sBw + tBw.y) + e1cB;

            { const bool g0 = vA0x > bst0A; bst0A = g0 ? vA0x : bst0A; bid0A = g0 ? ivA.x : bid0A;
              const bool g1 = vA1x > bst1A; bst1A = g1 ? vA1x : bst1A; bid1A = g1 ? ivA.x : bid1A; }
            { const bool g0 = vB0x > bst0B; bst0B = g0 ? vB0x : bst0B; bid0B = g0 ? ivB.x : bid0B;
              const bool g1 = vB1x > bst1B; bst1B = g1 ? vB1x : bst1B; bid1B = g1 ? ivB.x : bid1B; }
            { const bool g0 = vA0y > bst0A; bst0A = g0 ? vA0y : bst0A; bid0A = g0 ? ivA.y : bid0A;
              const bool g1 = vA1y > bst1A; bst1A = g1 ? vA1y : bst1A; bid1A = g1 ? ivA.y : bid1A; }
            { const bool g0 = vB0y > bst0B; bst0B = g0 ? vB0y : bst0B; bid0B = g0 ? ivB.y : bid0B;
              const bool g1 = vB1y > bst1B; bst1B = g1 ? vB1y : bst1B; bid1B = g1 ? ivB.y : bid1B; }
            { const bool g0 = vA0z > bst0A; bst0A = g0 ? vA0z : bst0A; bid0A = g0 ? ivA.z : bid0A;
              const bool g1 = vA1z > bst1A; bst1A = g1 ? vA1z : bst1A; bid1A = g1 ? ivA.z : bid1A; }
            { const bool g0 = vB0z > bst0B; bst0B = g0 ? vB0z : bst0B; bid0B = g0 ? ivB.z : bid0B;
              const bool g1 = vB1z > bst1B; bst1B = g1 ? vB1z : bst1B; bid1B = g1 ? ivB.z : bid1B; }
            { const bool g0 = vA0w > bst0A; bst0A = g0 ? vA0w : bst0A; bid0A = g0 ? ivA.w : bid0A;
              const bool g1 = vA1w > bst1A; bst1A = g1 ? vA1w : bst1A; bid1A = g1 ? ivA.w : bid1A; }
            { const bool g0 = vB0w > bst0B; bst0B = g0 ? vB0w : bst0B; bid0B = g0 ? ivB.w : bid0B;
              const bool g1 = vB1w > bst1B; bst1B = g1 ? vB1w : bst1B; bid1B = g1 ? ivB.w : bid1B; }
        }

        // history always records the argmax; mask only gates the score.
        hpA[lane]      = (unsigned char)bid0A;
        hpB[lane]      = (unsigned char)bid0B;
        hpA[lane + 32] = (unsigned char)bid1A;
        hpB[lane + 32] = (unsigned char)bid1B;

        s0A = mcA ? bst0A : s0A;
        s0B = mcB ? bst0B : s0B;
        s1A = mcA ? bst1A : s1A;
        s1B = mcB ? bst1B : s1B;

        // ---- thresholds (interleaved) -> ballots -> lists (parity q) ----
        const float thrA = warp_max_f32_redux(fmaxf(s0A, s1A)) + thrD;
        const float thrB = warp_max_f32_redux(fmaxf(s0B, s1B)) + thrD;
        const unsigned a0 = __ballot_sync(0xFFFFFFFFu, s0A >= thrA);
        const unsigned a1 = __ballot_sync(0xFFFFFFFFu, s1A >= thrA);
        const unsigned b0 = __ballot_sync(0xFFFFFFFFu, s0B >= thrB);
        const unsigned b1 = __ballot_sync(0xFFFFFFFFu, s1B >= thrB);
        nlA = __popc(a0) + __popc(a1);
        nlB = __popc(b0) + __popc(b1);

        const int q = p ^ 1;
        score_sh[w][0][q][lane]      = s0A;
        score_sh[w][1][q][lane]      = s0B;
        score_sh[w][0][q][lane + 32] = s1A;
        score_sh[w][1][q][lane + 32] = s1B;
        if ((a0 >> lane) & 1u) live_sh[w][0][q][__popc(a0 & lanemask)] = lane;
        if ((a1 >> lane) & 1u) live_sh[w][0][q][__popc(a0) + __popc(a1 & lanemask)] = lane + 32;
        if ((b0 >> lane) & 1u) live_sh[w][1][q][__popc(b0 & lanemask)] = lane;
        if ((b1 >> lane) & 1u) live_sh[w][1][q][__popc(b0) + __popc(b1 & lanemask)] = lane + 32;
        if (lane < 4) {
            live_sh[w][0][q][nlA + lane] = KK;
            live_sh[w][1][q][nlB + lane] = KK;
        }
        __syncwarp();

        // ---- prefetch e / mask for t+1 (both batches) ----
        const int tn  = (t + 1 < TT) ? (t + 1) : (TT - 1);
        const int off = (tn & 7) * KK;
        e0cA = em_sh[w][0][ebuf][off + lane];
        e0cB = em_sh[w][1][ebuf][off + lane];
        e1cA = em_sh[w][0][ebuf][off + 32 + lane];
        e1cB = em_sh[w][1][ebuf][off + 32 + lane];
        mcA  = smask_sh[w][0][tn];
        mcB  = smask_sh[w][1][tn];

        p = q;
        hpA += KK;
        hpB += KK;
    }

    // ---- final: + end_transitions, first-index argmax (per batch) ----
    {
        const float et0 = end_t[lane];
        const float et1 = end_t[lane + 32];
        const float vA0 = s0A + et0, vA1 = s1A + et1;
        const float vB0 = s0B + et0, vB1 = s1B + et1;
        float bvA; int biA;
        if (vA1 > vA0) { bvA = vA1; biA = lane + 32; } else { bvA = vA0; biA = lane; }
        float bvB; int biB;
        if (vB1 > vB0) { bvB = vB1; biB = lane + 32; } else { bvB = vB0; biB = lane; }
#pragma unroll
        for (int d = 16; d; d >>= 1) {
            const float voA = __shfl_xor_sync(0xFFFFFFFFu, bvA, d);
            const int   ioA = __shfl_xor_sync(0xFFFFFFFFu, biA, d);
            if (voA > bvA || (voA == bvA && ioA < biA)) { bvA = voA; biA = ioA; }
            const float voB = __shfl_xor_sync(0xFFFFFFFFu, bvB, d);
            const int   ioB = __shfl_xor_sync(0xFFFFFFFFu, biB, d);
            if (voB > bvB || (voB == bvB && ioB < biB)) { bvB = voB; biB = ioB; }
        }
        if (lane == 0) { g_best[bA] = biA; g_best[bB] = biB; }
    }
}

// ---------------------------------------------------------------------------
// Backtrace: one block per batch. Stage the 32KB history slab + mask into
// shared, then one thread walks the dependent chain at LDS latency.
// Output tags written as FLOAT32 (harness output dtype).
// ---------------------------------------------------------------------------
__global__ __launch_bounds__(256) void viterbi_backtrace(
    const int*  __restrict__ mask,   // [B, T]
    float*      __restrict__ out)    // [B, T] float32 tags
{
    const int b = blockIdx.x;
    __shared__ unsigned char h[TT * KK];   // 32 KB
    __shared__ int msk[TT];                // 2 KB

    const uint4* src = (const uint4*)(g_hist + (size_t)b * TT * KK);
    uint4* dst = (uint4*)h;
#pragma unroll 4
    for (int k = threadIdx.x; k < (TT * KK) / 16; k += blockDim.x)
        dst[k] = src[k];
    for (int t = threadIdx.x; t < TT; t += blockDim.x)
        msk[t] = mask[b * TT + t];
    __syncthreads();

    if (threadIdx.x == 0) {
        int tag = g_best[b];
        out[b * TT + (TT - 1)] = (float)tag;
        for (int t = TT - 1; t >= 1; --t) {
            const int prev = h[t * KK + tag];
            tag = msk[t] ? prev : tag;
            out[b * TT + t - 1] = (float)tag;
        }
    }
}

extern "C" void kernel_launch(void* const* d_in, const int* in_sizes, int n_in,
                              void* d_out, int out_size)
{
    // Bind inputs by element count:
    //   16777216 -> emissions, 262144 -> attn_mask, 4096 -> transitions,
    //   64 -> start_transitions (first), end_transitions (second)
    const float* emissions = nullptr;
    const int*   attn_mask = nullptr;
    const float* start_t   = nullptr;
    const float* end_t     = nullptr;
    const float* trans     = nullptr;

    for (int i = 0; i < n_in; ++i) {
        const int sz = in_sizes[i];
        if (sz == BB * TT * KK)      emissions = (const float*)d_in[i];
        else if (sz == BB * TT)      attn_mask = (const int*)d_in[i];
        else if (sz == KK * KK)      trans     = (const float*)d_in[i];
        else if (sz == KK) {
            if (!start_t) start_t = (const float*)d_in[i];
            else          end_t   = (const float*)d_in[i];
        }
    }

    float* out = (float*)d_out;  // [512,512] float32 tag values

    viterbi_forward<<<BB / 4, 64>>>(emissions, attn_mask, start_t, end_t, trans);
    viterbi_backtrace<<<BB, 256>>>(attn_mask, out);
}